// round 15
// baseline (speedup 1.0000x reference)
#include <cuda_runtime.h>
#include <cuda_fp16.h>
#include <cstdint>
#include <math.h>
#include <float.h>

#define N_NODES 100000
#define N_EDGES 1600000
#define DIM 128
#define NB 128
#define NEG 0.01f
#define PREP_BLOCKS 98   // ceil(100000/1024)
#define TILES 782        // ceil(100000/128)
#define CAP 128          // bucket capacity per node (mean deg 16; P(>=128) ~ 0)

// ---------------- scratch (static device globals; no allocation) ----------------
__device__ int g_deg[2][N_NODES];            // zeroed by one cudaMemsetAsync per call
__device__ __align__(16) uint2 g_xh[2][(size_t)N_NODES * 32]; // pre-scaled x̂ fp16 (dinv[src]*x)
__device__ float  g_dinv[2][N_NODES];
__device__ int    g_buck[2][(size_t)N_NODES * CAP];           // padded CSR buckets (src per slot)
// A operand in mma-fragment layout: frag (tile, rb(8), kc(8)) = 256 halves, thread-contiguous
__device__ __align__(16) __half g_Ah[2][(size_t)TILES * 64 * 256];
__device__ float g_pool[2 * NB * DIM];

__device__ __forceinline__ float lrelu(float v) { return v >= 0.f ? v : NEG * v; }

__device__ __forceinline__ void atomicMaxFloat(float* addr, float v) {
    if (v >= 0.f) atomicMax((int*)addr, __float_as_int(v));
    else          atomicMin((unsigned int*)addr, __float_as_uint(v));
}

// mma.sync m16n8k16 fp16 in / fp32 accum (sm_80 PTX; legal on compute_103)
#define MMA4(c, a, bb0, bb1) \
    asm volatile("mma.sync.aligned.m16n8k16.row.col.f32.f16.f16.f32 " \
        "{%0,%1,%2,%3}, {%4,%5,%6,%7}, {%8,%9}, {%0,%1,%2,%3};" \
        : "+f"((c)[0]), "+f"((c)[1]), "+f"((c)[2]), "+f"((c)[3]) \
        : "r"((a).x), "r"((a).y), "r"((a).z), "r"((a).w), "r"(bb0), "r"(bb1))

// ---------------- launch 1: bucket fill (count + scatter in one pass) ----------------
__global__ void k_fill(const int* __restrict__ row0, const int* __restrict__ col0,
                       const int* __restrict__ row1, const int* __restrict__ col1) {
    int p = blockIdx.y;
    const int* row = p ? row1 : row0;
    const int* col = p ? col1 : col0;
    int e = blockIdx.x * blockDim.x + threadIdx.x;
    if (e < N_EDGES) {
        int d = col[e];
        int pos = atomicAdd(&g_deg[p][d], 1);
        g_buck[p][(size_t)d * CAP + pos] = row[e];
    }
}

// ---------------- launch 2: dinv + pool init + x̂ transcode ----------------
__global__ void k_prep(const float* __restrict__ x0, const float* __restrict__ x1) {
    const int p = blockIdx.y;
    const int b = blockIdx.x;
    const int t = threadIdx.x;
    const int i = b * 1024 + t;
    const int lane = t & 31;

    if (i < N_NODES) g_dinv[p][i] = rsqrtf((float)(g_deg[p][i] + 1));   // +1 self loop
    if (b == 0) {
        #pragma unroll
        for (int it = 0; it < 16; it++)
            g_pool[p * NB * DIM + it * 1024 + t] = -FLT_MAX;
    }

    // transcode: x̂ = dinv[src] * x (fp16), coalesced, 32 nodes/warp
    {
        const float4* xs = (const float4*)(p ? x1 : x0);
        const int w = t >> 5;
        const int nb = b * 1024 + w * 32;
        for (int nd = 0; nd < 32; nd++) {
            int i2 = nb + nd;
            if (i2 >= N_NODES) break;
            float s = rsqrtf((float)(g_deg[p][i2] + 1));
            float4 xv = xs[(size_t)i2 * 32 + lane];
            __half2 h0 = __floats2half2_rn(s * xv.x, s * xv.y);
            __half2 h1 = __floats2half2_rn(s * xv.z, s * xv.w);
            uint2 o;
            o.x = *(unsigned*)&h0; o.y = *(unsigned*)&h1;
            g_xh[p][(size_t)i2 * 32 + lane] = o;
        }
    }
}

// ---------------- launch 3: gather (pre-scaled fp16) -> mma-frag fp16 A ----------------
__global__ void k_gather() {
    int p = blockIdx.y;
    const char* xb = (const char*)g_xh[p];       // byte base; row = 256B
    int gw = (blockIdx.x * blockDim.x + threadIdx.x) >> 5;
    int lane = threadIdx.x & 31;
    if (gw >= N_NODES) return;
    const int i = gw;
    const float di = g_dinv[p][i];
    const unsigned lb = (unsigned)lane * 8u;     // lane byte offset within row
    const int* csr = g_buck[p] + (size_t)i * CAP;

    float4 acc;
    {
        uint2 u = *(const uint2*)(xb + (unsigned)i * 256u + lb);   // self term
        float2 fa = __half22float2(*(__half2*)&u.x), fb = __half22float2(*(__half2*)&u.y);
        acc.x = fa.x; acc.y = fa.y; acc.z = fb.x; acc.w = fb.y;
    }

    int j = 0;
    const int s1 = g_deg[p][i];
    for (; j + 4 <= s1; j += 4) {
        unsigned oa = (unsigned)csr[j]     * 256u + lb;
        unsigned ob = (unsigned)csr[j + 1] * 256u + lb;
        unsigned oc = (unsigned)csr[j + 2] * 256u + lb;
        unsigned od = (unsigned)csr[j + 3] * 256u + lb;
        uint2 ua = *(const uint2*)(xb + oa);
        uint2 ub = *(const uint2*)(xb + ob);
        uint2 uc = *(const uint2*)(xb + oc);
        uint2 ud = *(const uint2*)(xb + od);
        float2 a0 = __half22float2(*(__half2*)&ua.x), a1 = __half22float2(*(__half2*)&ua.y);
        float2 b0 = __half22float2(*(__half2*)&ub.x), b1 = __half22float2(*(__half2*)&ub.y);
        float2 c0 = __half22float2(*(__half2*)&uc.x), c1 = __half22float2(*(__half2*)&uc.y);
        float2 d0 = __half22float2(*(__half2*)&ud.x), d1 = __half22float2(*(__half2*)&ud.y);
        acc.x += a0.x + b0.x + c0.x + d0.x;
        acc.y += a0.y + b0.y + c0.y + d0.y;
        acc.z += a1.x + b1.x + c1.x + d1.x;
        acc.w += a1.y + b1.y + c1.y + d1.y;
    }
    for (; j < s1; j++) {
        uint2 u = *(const uint2*)(xb + (unsigned)csr[j] * 256u + lb);
        float2 f0 = __half22float2(*(__half2*)&u.x), f1 = __half22float2(*(__half2*)&u.y);
        acc.x += f0.x; acc.y += f0.y; acc.z += f1.x; acc.w += f1.y;
    }
    acc.x *= di; acc.y *= di; acc.z *= di; acc.w *= di;

    __half2 hp0 = __floats2half2_rn(acc.x, acc.y);
    __half2 hp1 = __floats2half2_rn(acc.z, acc.w);

    // fragment-layout offsets: lane j handles k = j*4..j*4+3
    const int tile = i >> 7;
    const int rb = (i >> 4) & 7;          // 16-row frag within tile
    const int r16 = i & 15;
    const int kc = lane >> 2;             // k-chunk
    const int kl = (lane & 3) * 4;        // k within chunk (0,4,8,12)
    const int lane_f = ((r16 & 7) << 2) + ((kl & 7) >> 1);
    const int reg = ((r16 >> 3) & 1) + ((kl >> 3) << 1);
    const size_t base = ((((size_t)tile * 8 + rb) * 8 + kc) << 8) + (size_t)(lane_f * 8 + reg * 2);

    __half* Ah = g_Ah[p];
    *(__half2*)&Ah[base]     = hp0;       // (k, k+1)
    *(__half2*)&Ah[base + 8] = hp1;       // (k+2, k+3)
}

// ---------------- launch 4 (CAPTURED): mma.sync fp16 GEMM, 2 M-frags/warp ----------------
// 512 threads: 16 warps = 8 M-frags x 2 N-halves; each warp owns 2 tiles' frags (M=256/block).
// W in smem as uint2 frags: sW[nb(16)][kc(8)][lane(32)] = {b0h, b1h}; 1 LDS.64 feeds 2 MMAs.
#define SMEM_GEMM (4096 * 8 + 512)

__global__ void __launch_bounds__(512)
k_gemm_pool(const float* __restrict__ W0, const float* __restrict__ b0,
            const float* __restrict__ W1, const float* __restrict__ b1,
            const int* __restrict__ batch0, const int* __restrict__ batch1) {
    extern __shared__ uint2 sW[];                // 4096 uint2 = 32KB
    float* s_bias = (float*)(sW + 4096);

    const int p = blockIdx.y;
    const int t0 = blockIdx.x * 2;               // first of 2 tiles
    const float* __restrict__ W     = p ? W1 : W0;
    const float* __restrict__ bias  = p ? b1 : b0;
    const int*   __restrict__ batch = p ? batch1 : batch0;
    const int tid = threadIdx.x, lane = tid & 31, w = tid >> 5;
    const int w_m = w & 7, nh = w >> 3;

    // stage W -> fragment-ordered smem (one-time, 8 uint2/thread)
    #pragma unroll
    for (int it = 0; it < 8; it++) {
        int idx = tid + it * 512;                // 0..4095
        int lane_s = idx & 31;
        int kc_s = (idx >> 5) & 7;
        int nb_s = idx >> 8;                     // 0..15
        int n = nb_s * 8 + (lane_s >> 2);
        int k0 = (kc_s * 8 + (lane_s & 3)) * 2;  // pairs at k0,k0+1 and k0+8,k0+9
        float w00 = W[k0 * 128 + n];
        float w01 = W[(k0 + 1) * 128 + n];
        float w10 = W[(k0 + 8) * 128 + n];
        float w11 = W[(k0 + 9) * 128 + n];
        __half2 ph0 = __floats2half2_rn(w00, w01);
        __half2 ph1 = __floats2half2_rn(w10, w11);
        uint2 frag;
        frag.x = *(unsigned*)&ph0; frag.y = *(unsigned*)&ph1;
        sW[idx] = frag;
    }
    if (tid < 128) s_bias[tid] = bias[tid];
    __syncthreads();

    float acc[2][8][4];
    #pragma unroll
    for (int tt = 0; tt < 2; tt++)
        #pragma unroll
        for (int jj = 0; jj < 8; jj++)
            #pragma unroll
            for (int q = 0; q < 4; q++) acc[tt][jj][q] = 0.f;

    const __half* Ah = g_Ah[p];
    const size_t abase0 = ((size_t)t0 * 8 + w_m) * 8;
    const size_t abase1 = ((size_t)(t0 + 1) * 8 + w_m) * 8;
    #pragma unroll
    for (int kc = 0; kc < 8; kc++) {
        uint4 ah0 = *(const uint4*)&Ah[((abase0 + kc) << 8) + lane * 8];
        uint4 ah1 = *(const uint4*)&Ah[((abase1 + kc) << 8) + lane * 8];
        #pragma unroll
        for (int jj = 0; jj < 8; jj++) {
            uint2 bf = sW[(((nh * 8 + jj) * 8 + kc) << 5) + lane];   // one LDS.64, two MMAs
            MMA4(acc[0][jj], ah0, bf.x, bf.y);
            MMA4(acc[1][jj], ah1, bf.x, bf.y);
        }
    }

    // epilogue: segment_max into pool (per tile-half)
    float* pool = &g_pool[p * NB * DIM];
    #pragma unroll
    for (int tt = 0; tt < 2; tt++) {
        const int r_base = (t0 + tt) * 128 + w_m * 16;
        const bool full = (r_base + 15 < N_NODES);
        const bool any  = (r_base < N_NODES);
        int btA = any ? batch[r_base] : -1;
        int btB = full ? batch[r_base + 15] : -2;

        if (full && btA == btB) {
            #pragma unroll
            for (int jj = 0; jj < 8; jj++) {
                float m0 = fmaxf(acc[tt][jj][0], acc[tt][jj][2]);
                float m1 = fmaxf(acc[tt][jj][1], acc[tt][jj][3]);
                #pragma unroll
                for (int o = 4; o <= 16; o <<= 1) {
                    m0 = fmaxf(m0, __shfl_xor_sync(0xffffffffu, m0, o));
                    m1 = fmaxf(m1, __shfl_xor_sync(0xffffffffu, m1, o));
                }
                if ((lane >> 2) == 0) {
                    int c = (nh * 8 + jj) * 8 + (lane & 3) * 2;
                    atomicMaxFloat(&pool[btA * DIM + c],     lrelu(m0 + s_bias[c]));
                    atomicMaxFloat(&pool[btA * DIM + c + 1], lrelu(m1 + s_bias[c + 1]));
                }
            }
        } else if (any) {
            int r0 = r_base + (lane >> 2), r1 = r0 + 8;
            int bt0 = (r0 < N_NODES) ? batch[r0] : -1;
            int bt1 = (r1 < N_NODES) ? batch[r1] : -1;
            #pragma unroll
            for (int jj = 0; jj < 8; jj++) {
                int c = (nh * 8 + jj) * 8 + (lane & 3) * 2;
                if (bt0 >= 0) {
                    atomicMaxFloat(&pool[bt0 * DIM + c],     lrelu(acc[tt][jj][0] + s_bias[c]));
                    atomicMaxFloat(&pool[bt0 * DIM + c + 1], lrelu(acc[tt][jj][1] + s_bias[c + 1]));
                }
                if (bt1 >= 0) {
                    atomicMaxFloat(&pool[bt1 * DIM + c],     lrelu(acc[tt][jj][2] + s_bias[c]));
                    atomicMaxFloat(&pool[bt1 * DIM + c + 1], lrelu(acc[tt][jj][3] + s_bias[c + 1]));
                }
            }
        }
    }
}

// ---------------- launch 5: fused tail MLP (fcp both branches -> fc1 -> fc2 -> out) ----------------
__global__ void __launch_bounds__(256)
k_tail(const float* __restrict__ fcp1W, const float* __restrict__ fcp1B,
       const float* __restrict__ fcp2W, const float* __restrict__ fcp2B,
       const float* __restrict__ fc1W,  const float* __restrict__ fc1B,
       const float* __restrict__ fc2W,  const float* __restrict__ fc2B,
       const float* __restrict__ outW,  const float* __restrict__ outB,
       float* __restrict__ out) {
    const int r = blockIdx.x, t = threadIdx.x;
    __shared__ float pl[256];   // pool rows: [0:128)=branch0, [128:256)=branch1
    __shared__ float c[256];    // concat(g1, g2)
    __shared__ float c1s[256];
    __shared__ float c2s[64];

    pl[t] = g_pool[(t < 128 ? 0 : NB * DIM) + r * 128 + (t & 127)];
    __syncthreads();

    {   // fc_p per branch
        const float* Wp = (t < 128) ? fcp1W : fcp2W;
        const float* bp = (t < 128) ? fcp1B : fcp2B;
        const float* src = (t < 128) ? pl : (pl + 128);
        int d = t & 127;
        float s = bp[d];
        #pragma unroll 8
        for (int k = 0; k < 128; k++) s += src[k] * Wp[k * 128 + d];
        c[t] = lrelu(s);
    }
    __syncthreads();

    {   // fc1: 256 -> 256
        float s = fc1B[t];
        #pragma unroll 8
        for (int k = 0; k < 256; k++) s += c[k] * fc1W[k * 256 + t];
        c1s[t] = lrelu(s);
    }
    __syncthreads();

    if (t < 64) {   // fc2: 256 -> 64
        float s = fc2B[t];
        #pragma unroll 8
        for (int k = 0; k < 256; k++) s += c1s[k] * fc2W[k * 64 + t];
        c2s[t] = lrelu(s);
    }
    __syncthreads();

    if (t < 32) {   // out: 64 -> 1 + sigmoid
        float v = c2s[t] * outW[t] + c2s[t + 32] * outW[t + 32];
        #pragma unroll
        for (int o = 16; o; o >>= 1) v += __shfl_xor_sync(0xffffffffu, v, o);
        if (t == 0) out[r] = 1.f / (1.f + expf(-(v + outB[0])));
    }
}

// ---------------- host launcher ----------------
extern "C" void kernel_launch(void* const* d_in, const int* in_sizes, int n_in,
                              void* d_out, int out_size) {
    int ix[2], ie[2], ib[2];
    if (in_sizes[1] == N_NODES * DIM) {
        ix[0] = 0; ix[1] = 1; ie[0] = 2; ie[1] = 3; ib[0] = 4; ib[1] = 5;   // dict order
    } else {
        ix[0] = 0; ie[0] = 1; ib[0] = 2; ix[1] = 3; ie[1] = 4; ib[1] = 5;   // signature order
    }
    const float* x0 = (const float*)d_in[ix[0]];
    const float* x1 = (const float*)d_in[ix[1]];
    const int* row0 = (const int*)d_in[ie[0]];
    const int* col0 = row0 + N_EDGES;
    const int* row1 = (const int*)d_in[ie[1]];
    const int* col1 = row1 + N_EDGES;
    const int* bat0 = (const int*)d_in[ib[0]];
    const int* bat1 = (const int*)d_in[ib[1]];

    const float* convW0 = (const float*)d_in[6];
    const float* convB0 = (const float*)d_in[7];
    const float* convW1 = (const float*)d_in[8];
    const float* convB1 = (const float*)d_in[9];
    const float* fcp1W = (const float*)d_in[10];
    const float* fcp1B = (const float*)d_in[11];
    const float* fcp2W = (const float*)d_in[12];
    const float* fcp2B = (const float*)d_in[13];
    const float* fc1W  = (const float*)d_in[14];
    const float* fc1B  = (const float*)d_in[15];
    const float* fc2W  = (const float*)d_in[16];
    const float* fc2B  = (const float*)d_in[17];
    const float* outW  = (const float*)d_in[18];
    const float* outB  = (const float*)d_in[19];

    static bool attr_done = false;
    if (!attr_done) {
        cudaFuncSetAttribute(k_gemm_pool, cudaFuncAttributeMaxDynamicSharedMemorySize, SMEM_GEMM);
        attr_done = true;
    }

    void* degPtr = nullptr;
    cudaGetSymbolAddress(&degPtr, g_deg);
    cudaMemsetAsync(degPtr, 0, 2 * N_NODES * sizeof(int));

    k_fill<<<dim3((N_EDGES + 255) / 256, 2), 256>>>(row0, col0, row1, col1); // launch 1
    k_prep<<<dim3(PREP_BLOCKS, 2), 1024>>>(x0, x1);                          // launch 2
    k_gather<<<dim3((N_NODES * 32 + 255) / 256, 2), 256>>>();                // launch 3
    k_gemm_pool<<<dim3((TILES + 1) / 2, 2), 512, SMEM_GEMM>>>(convW0, convB0, convW1, convB1, bat0, bat1); // launch 4 (captured)
    k_tail<<<NB, 256>>>(fcp1W, fcp1B, fcp2W, fcp2B, fc1W, fc1B, fc2W, fc2B,
                        outW, outB, (float*)d_out);                          // launch 5
}

// round 16
// speedup vs baseline: 1.0423x; 1.0423x over previous
#include <cuda_runtime.h>
#include <cuda_fp16.h>
#include <cstdint>
#include <math.h>
#include <float.h>

#define N_NODES 100000
#define N_EDGES 1600000
#define DIM 128
#define NB 128
#define NEG 0.01f
#define PREP_BLOCKS 98   // ceil(100000/1024)
#define TILES 782        // ceil(100000/128)
#define CAP 128          // bucket capacity per node (mean deg 16; P(>=128) ~ 0)

// ---------------- scratch (static device globals; no allocation) ----------------
__device__ int g_deg[2][N_NODES];            // zeroed by one cudaMemsetAsync per call
__device__ __align__(16) uint2 g_xh[2][(size_t)N_NODES * 32]; // pre-scaled x̂ fp16 (dinv[src]*x)
__device__ float  g_dinv[2][N_NODES];
__device__ int    g_buck[2][(size_t)N_NODES * CAP];           // padded CSR buckets (src per slot)
// A operand in mma-fragment layout: frag (tile, rb(8), kc(8)) = 256 halves, thread-contiguous
__device__ __align__(16) __half g_Ah[2][(size_t)TILES * 64 * 256];
__device__ float g_pool[2 * NB * DIM];

__device__ __forceinline__ float lrelu(float v) { return v >= 0.f ? v : NEG * v; }

__device__ __forceinline__ void atomicMaxFloat(float* addr, float v) {
    if (v >= 0.f) atomicMax((int*)addr, __float_as_int(v));
    else          atomicMin((unsigned int*)addr, __float_as_uint(v));
}

// mma.sync m16n8k16 fp16 in / fp32 accum (sm_80 PTX; legal on compute_103)
#define MMA4(c, a, bb0, bb1) \
    asm volatile("mma.sync.aligned.m16n8k16.row.col.f32.f16.f16.f32 " \
        "{%0,%1,%2,%3}, {%4,%5,%6,%7}, {%8,%9}, {%0,%1,%2,%3};" \
        : "+f"((c)[0]), "+f"((c)[1]), "+f"((c)[2]), "+f"((c)[3]) \
        : "r"((a).x), "r"((a).y), "r"((a).z), "r"((a).w), "r"(bb0), "r"(bb1))

// ---------------- launch 1: bucket fill (count + scatter in one pass) ----------------
__global__ void k_fill(const int* __restrict__ row0, const int* __restrict__ col0,
                       const int* __restrict__ row1, const int* __restrict__ col1) {
    int p = blockIdx.y;
    const int* row = p ? row1 : row0;
    const int* col = p ? col1 : col0;
    int e = blockIdx.x * blockDim.x + threadIdx.x;
    if (e < N_EDGES) {
        int d = col[e];
        int pos = atomicAdd(&g_deg[p][d], 1);
        g_buck[p][(size_t)d * CAP + pos] = row[e];
    }
}

// ---------------- launch 2: dinv + pool init + x̂ transcode ----------------
__global__ void k_prep(const float* __restrict__ x0, const float* __restrict__ x1) {
    const int p = blockIdx.y;
    const int b = blockIdx.x;
    const int t = threadIdx.x;
    const int i = b * 1024 + t;
    const int lane = t & 31;

    if (i < N_NODES) g_dinv[p][i] = rsqrtf((float)(g_deg[p][i] + 1));   // +1 self loop
    if (b == 0) {
        #pragma unroll
        for (int it = 0; it < 16; it++)
            g_pool[p * NB * DIM + it * 1024 + t] = -FLT_MAX;
    }

    // transcode: x̂ = dinv[src] * x (fp16), coalesced, 32 nodes/warp
    {
        const float4* xs = (const float4*)(p ? x1 : x0);
        const int w = t >> 5;
        const int nb = b * 1024 + w * 32;
        for (int nd = 0; nd < 32; nd++) {
            int i2 = nb + nd;
            if (i2 >= N_NODES) break;
            float s = rsqrtf((float)(g_deg[p][i2] + 1));
            float4 xv = xs[(size_t)i2 * 32 + lane];
            __half2 h0 = __floats2half2_rn(s * xv.x, s * xv.y);
            __half2 h1 = __floats2half2_rn(s * xv.z, s * xv.w);
            uint2 o;
            o.x = *(unsigned*)&h0; o.y = *(unsigned*)&h1;
            g_xh[p][(size_t)i2 * 32 + lane] = o;
        }
    }
}

// ---------------- launch 3: gather (pre-scaled fp16) -> mma-frag fp16 A ----------------
__global__ void k_gather() {
    int p = blockIdx.y;
    const char* xb = (const char*)g_xh[p];       // byte base; row = 256B
    int gw = (blockIdx.x * blockDim.x + threadIdx.x) >> 5;
    int lane = threadIdx.x & 31;
    if (gw >= N_NODES) return;
    const int i = gw;
    const float di = g_dinv[p][i];
    const unsigned lb = (unsigned)lane * 8u;     // lane byte offset within row
    const int* csr = g_buck[p] + (size_t)i * CAP;

    float4 acc;
    {
        uint2 u = *(const uint2*)(xb + (unsigned)i * 256u + lb);   // self term
        float2 fa = __half22float2(*(__half2*)&u.x), fb = __half22float2(*(__half2*)&u.y);
        acc.x = fa.x; acc.y = fa.y; acc.z = fb.x; acc.w = fb.y;
    }

    int j = 0;
    const int s1 = g_deg[p][i];
    for (; j + 4 <= s1; j += 4) {
        unsigned oa = (unsigned)csr[j]     * 256u + lb;
        unsigned ob = (unsigned)csr[j + 1] * 256u + lb;
        unsigned oc = (unsigned)csr[j + 2] * 256u + lb;
        unsigned od = (unsigned)csr[j + 3] * 256u + lb;
        uint2 ua = *(const uint2*)(xb + oa);
        uint2 ub = *(const uint2*)(xb + ob);
        uint2 uc = *(const uint2*)(xb + oc);
        uint2 ud = *(const uint2*)(xb + od);
        float2 a0 = __half22float2(*(__half2*)&ua.x), a1 = __half22float2(*(__half2*)&ua.y);
        float2 b0 = __half22float2(*(__half2*)&ub.x), b1 = __half22float2(*(__half2*)&ub.y);
        float2 c0 = __half22float2(*(__half2*)&uc.x), c1 = __half22float2(*(__half2*)&uc.y);
        float2 d0 = __half22float2(*(__half2*)&ud.x), d1 = __half22float2(*(__half2*)&ud.y);
        acc.x += a0.x + b0.x + c0.x + d0.x;
        acc.y += a0.y + b0.y + c0.y + d0.y;
        acc.z += a1.x + b1.x + c1.x + d1.x;
        acc.w += a1.y + b1.y + c1.y + d1.y;
    }
    for (; j < s1; j++) {
        uint2 u = *(const uint2*)(xb + (unsigned)csr[j] * 256u + lb);
        float2 f0 = __half22float2(*(__half2*)&u.x), f1 = __half22float2(*(__half2*)&u.y);
        acc.x += f0.x; acc.y += f0.y; acc.z += f1.x; acc.w += f1.y;
    }
    acc.x *= di; acc.y *= di; acc.z *= di; acc.w *= di;

    __half2 hp0 = __floats2half2_rn(acc.x, acc.y);
    __half2 hp1 = __floats2half2_rn(acc.z, acc.w);

    // fragment-layout offsets: lane j handles k = j*4..j*4+3
    const int tile = i >> 7;
    const int rb = (i >> 4) & 7;          // 16-row frag within tile
    const int r16 = i & 15;
    const int kc = lane >> 2;             // k-chunk
    const int kl = (lane & 3) * 4;        // k within chunk (0,4,8,12)
    const int lane_f = ((r16 & 7) << 2) + ((kl & 7) >> 1);
    const int reg = ((r16 >> 3) & 1) + ((kl >> 3) << 1);
    const size_t base = ((((size_t)tile * 8 + rb) * 8 + kc) << 8) + (size_t)(lane_f * 8 + reg * 2);

    __half* Ah = g_Ah[p];
    *(__half2*)&Ah[base]     = hp0;       // (k, k+1)
    *(__half2*)&Ah[base + 8] = hp1;       // (k+2, k+3)
}

// ---------------- launch 4 (CAPTURED): mma.sync fp16 GEMM, frag-ordered W smem (R14 config) ----------------
// 512 threads: 16 warps = 8 M-frags x 2 N-halves. W in smem as uint2 frags:
// sW[nb(16)][kc(8)][lane(32)] = {b0h, b1h} -> one LDS.64 + one MMA per (jj,kc).
#define SMEM_GEMM (4096 * 8 + 512)

__global__ void __launch_bounds__(512, 2)
k_gemm_pool(const float* __restrict__ W0, const float* __restrict__ b0,
            const float* __restrict__ W1, const float* __restrict__ b1,
            const int* __restrict__ batch0, const int* __restrict__ batch1) {
    extern __shared__ uint2 sW[];                // 4096 uint2 = 32KB
    float* s_bias = (float*)(sW + 4096);

    const int p = blockIdx.y, tile = blockIdx.x;
    const float* __restrict__ W     = p ? W1 : W0;
    const float* __restrict__ bias  = p ? b1 : b0;
    const int*   __restrict__ batch = p ? batch1 : batch0;
    const int tid = threadIdx.x, lane = tid & 31, w = tid >> 5;
    const int w_m = w & 7, nh = w >> 3;

    // stage W -> fragment-ordered smem (one-time, 8 uint2/thread)
    #pragma unroll
    for (int it = 0; it < 8; it++) {
        int idx = tid + it * 512;                // 0..4095
        int lane_s = idx & 31;
        int kc_s = (idx >> 5) & 7;
        int nb_s = idx >> 8;                     // 0..15
        int n = nb_s * 8 + (lane_s >> 2);
        int k0 = (kc_s * 8 + (lane_s & 3)) * 2;  // pairs at k0,k0+1 and k0+8,k0+9
        float w00 = W[k0 * 128 + n];
        float w01 = W[(k0 + 1) * 128 + n];
        float w10 = W[(k0 + 8) * 128 + n];
        float w11 = W[(k0 + 9) * 128 + n];
        __half2 ph0 = __floats2half2_rn(w00, w01);
        __half2 ph1 = __floats2half2_rn(w10, w11);
        uint2 frag;
        frag.x = *(unsigned*)&ph0; frag.y = *(unsigned*)&ph1;
        sW[idx] = frag;
    }
    if (tid < 128) s_bias[tid] = bias[tid];
    __syncthreads();

    float acc[8][4];
    #pragma unroll
    for (int jj = 0; jj < 8; jj++)
        #pragma unroll
        for (int q = 0; q < 4; q++) acc[jj][q] = 0.f;

    const __half* Ah = g_Ah[p];
    const size_t abase = ((size_t)tile * 8 + w_m) * 8;
    #pragma unroll
    for (int kc = 0; kc < 8; kc++) {
        uint4 ah = *(const uint4*)&Ah[((abase + kc) << 8) + lane * 8];
        #pragma unroll
        for (int jj = 0; jj < 8; jj++) {
            uint2 bf = sW[(((nh * 8 + jj) * 8 + kc) << 5) + lane];   // one LDS.64
            MMA4(acc[jj], ah, bf.x, bf.y);
        }
    }

    // epilogue: segment_max into pool
    const int r_base = tile * 128 + w_m * 16;
    float* pool = &g_pool[p * NB * DIM];
    const bool full = (r_base + 15 < N_NODES);
    const bool any  = (r_base < N_NODES);
    int btA = any ? batch[r_base] : -1;
    int btB = full ? batch[r_base + 15] : -2;

    if (full && btA == btB) {
        #pragma unroll
        for (int jj = 0; jj < 8; jj++) {
            float m0 = fmaxf(acc[jj][0], acc[jj][2]);
            float m1 = fmaxf(acc[jj][1], acc[jj][3]);
            #pragma unroll
            for (int o = 4; o <= 16; o <<= 1) {
                m0 = fmaxf(m0, __shfl_xor_sync(0xffffffffu, m0, o));
                m1 = fmaxf(m1, __shfl_xor_sync(0xffffffffu, m1, o));
            }
            if ((lane >> 2) == 0) {
                int c = (nh * 8 + jj) * 8 + (lane & 3) * 2;
                atomicMaxFloat(&pool[btA * DIM + c],     lrelu(m0 + s_bias[c]));
                atomicMaxFloat(&pool[btA * DIM + c + 1], lrelu(m1 + s_bias[c + 1]));
            }
        }
    } else if (any) {
        int r0 = r_base + (lane >> 2), r1 = r0 + 8;
        int bt0 = (r0 < N_NODES) ? batch[r0] : -1;
        int bt1 = (r1 < N_NODES) ? batch[r1] : -1;
        #pragma unroll
        for (int jj = 0; jj < 8; jj++) {
            int c = (nh * 8 + jj) * 8 + (lane & 3) * 2;
            if (bt0 >= 0) {
                atomicMaxFloat(&pool[bt0 * DIM + c],     lrelu(acc[jj][0] + s_bias[c]));
                atomicMaxFloat(&pool[bt0 * DIM + c + 1], lrelu(acc[jj][1] + s_bias[c + 1]));
            }
            if (bt1 >= 0) {
                atomicMaxFloat(&pool[bt1 * DIM + c],     lrelu(acc[jj][2] + s_bias[c]));
                atomicMaxFloat(&pool[bt1 * DIM + c + 1], lrelu(acc[jj][3] + s_bias[c + 1]));
            }
        }
    }
}

// ---------------- launch 5: fused tail MLP (fcp both branches -> fc1 -> fc2 -> out) ----------------
__global__ void __launch_bounds__(256)
k_tail(const float* __restrict__ fcp1W, const float* __restrict__ fcp1B,
       const float* __restrict__ fcp2W, const float* __restrict__ fcp2B,
       const float* __restrict__ fc1W,  const float* __restrict__ fc1B,
       const float* __restrict__ fc2W,  const float* __restrict__ fc2B,
       const float* __restrict__ outW,  const float* __restrict__ outB,
       float* __restrict__ out) {
    const int r = blockIdx.x, t = threadIdx.x;
    __shared__ float pl[256];   // pool rows: [0:128)=branch0, [128:256)=branch1
    __shared__ float c[256];    // concat(g1, g2)
    __shared__ float c1s[256];
    __shared__ float c2s[64];

    pl[t] = g_pool[(t < 128 ? 0 : NB * DIM) + r * 128 + (t & 127)];
    __syncthreads();

    {   // fc_p per branch
        const float* Wp = (t < 128) ? fcp1W : fcp2W;
        const float* bp = (t < 128) ? fcp1B : fcp2B;
        const float* src = (t < 128) ? pl : (pl + 128);
        int d = t & 127;
        float s = bp[d];
        #pragma unroll 8
        for (int k = 0; k < 128; k++) s += src[k] * Wp[k * 128 + d];
        c[t] = lrelu(s);
    }
    __syncthreads();

    {   // fc1: 256 -> 256
        float s = fc1B[t];
        #pragma unroll 8
        for (int k = 0; k < 256; k++) s += c[k] * fc1W[k * 256 + t];
        c1s[t] = lrelu(s);
    }
    __syncthreads();

    if (t < 64) {   // fc2: 256 -> 64
        float s = fc2B[t];
        #pragma unroll 8
        for (int k = 0; k < 256; k++) s += c1s[k] * fc2W[k * 64 + t];
        c2s[t] = lrelu(s);
    }
    __syncthreads();

    if (t < 32) {   // out: 64 -> 1 + sigmoid
        float v = c2s[t] * outW[t] + c2s[t + 32] * outW[t + 32];
        #pragma unroll
        for (int o = 16; o; o >>= 1) v += __shfl_xor_sync(0xffffffffu, v, o);
        if (t == 0) out[r] = 1.f / (1.f + expf(-(v + outB[0])));
    }
}

// ---------------- host launcher ----------------
extern "C" void kernel_launch(void* const* d_in, const int* in_sizes, int n_in,
                              void* d_out, int out_size) {
    int ix[2], ie[2], ib[2];
    if (in_sizes[1] == N_NODES * DIM) {
        ix[0] = 0; ix[1] = 1; ie[0] = 2; ie[1] = 3; ib[0] = 4; ib[1] = 5;   // dict order
    } else {
        ix[0] = 0; ie[0] = 1; ib[0] = 2; ix[1] = 3; ie[1] = 4; ib[1] = 5;   // signature order
    }
    const float* x0 = (const float*)d_in[ix[0]];
    const float* x1 = (const float*)d_in[ix[1]];
    const int* row0 = (const int*)d_in[ie[0]];
    const int* col0 = row0 + N_EDGES;
    const int* row1 = (const int*)d_in[ie[1]];
    const int* col1 = row1 + N_EDGES;
    const int* bat0 = (const int*)d_in[ib[0]];
    const int* bat1 = (const int*)d_in[ib[1]];

    const float* convW0 = (const float*)d_in[6];
    const float* convB0 = (const float*)d_in[7];
    const float* convW1 = (const float*)d_in[8];
    const float* convB1 = (const float*)d_in[9];
    const float* fcp1W = (const float*)d_in[10];
    const float* fcp1B = (const float*)d_in[11];
    const float* fcp2W = (const float*)d_in[12];
    const float* fcp2B = (const float*)d_in[13];
    const float* fc1W  = (const float*)d_in[14];
    const float* fc1B  = (const float*)d_in[15];
    const float* fc2W  = (const float*)d_in[16];
    const float* fc2B  = (const float*)d_in[17];
    const float* outW  = (const float*)d_in[18];
    const float* outB  = (const float*)d_in[19];

    static bool attr_done = false;
    if (!attr_done) {
        cudaFuncSetAttribute(k_gemm_pool, cudaFuncAttributeMaxDynamicSharedMemorySize, SMEM_GEMM);
        attr_done = true;
    }

    void* degPtr = nullptr;
    cudaGetSymbolAddress(&degPtr, g_deg);
    cudaMemsetAsync(degPtr, 0, 2 * N_NODES * sizeof(int));

    k_fill<<<dim3((N_EDGES + 255) / 256, 2), 256>>>(row0, col0, row1, col1); // launch 1
    k_prep<<<dim3(PREP_BLOCKS, 2), 1024>>>(x0, x1);                          // launch 2
    k_gather<<<dim3((N_NODES * 32 + 255) / 256, 2), 256>>>();                // launch 3
    k_gemm_pool<<<dim3(TILES, 2), 512, SMEM_GEMM>>>(convW0, convB0, convW1, convB1, bat0, bat1); // launch 4 (captured)
    k_tail<<<NB, 256>>>(fcp1W, fcp1B, fcp2W, fcp2B, fc1W, fc1B, fc2W, fc2B,
                        outW, outB, (float*)d_out);                          // launch 5
}

// round 17
// speedup vs baseline: 1.0685x; 1.0252x over previous
#include <cuda_runtime.h>
#include <cuda_fp16.h>
#include <cstdint>
#include <math.h>
#include <float.h>

#define N_NODES 100000
#define N_EDGES 1600000
#define DIM 128
#define NB 128
#define NEG 0.01f
#define PREP_BLOCKS 98   // ceil(100000/1024)
#define TILES 782        // ceil(100000/128)
#define CAP 128          // bucket capacity per node (mean deg 16; P(>=128) ~ 0)

// ---------------- scratch (static device globals; no allocation) ----------------
__device__ int g_deg[2][N_NODES];            // zeroed by one cudaMemsetAsync per call
__device__ __align__(16) uint2 g_xh[2][(size_t)N_NODES * 32]; // pre-scaled x̂ fp16 (dinv[src]*x)
__device__ float  g_dinv[2][N_NODES];
__device__ __align__(16) int g_buck[2][(size_t)N_NODES * CAP]; // padded CSR buckets (src per slot)
// A operand in mma-fragment layout: frag (tile, rb(8), kc(8)) = 256 halves, thread-contiguous
__device__ __align__(16) __half g_Ah[2][(size_t)TILES * 64 * 256];
__device__ float g_pool[2 * NB * DIM];

__device__ __forceinline__ float lrelu(float v) { return v >= 0.f ? v : NEG * v; }

__device__ __forceinline__ void atomicMaxFloat(float* addr, float v) {
    if (v >= 0.f) atomicMax((int*)addr, __float_as_int(v));
    else          atomicMin((unsigned int*)addr, __float_as_uint(v));
}

// mma.sync m16n8k16 fp16 in / fp32 accum (sm_80 PTX; legal on compute_103)
#define MMA4(c, a, bb0, bb1) \
    asm volatile("mma.sync.aligned.m16n8k16.row.col.f32.f16.f16.f32 " \
        "{%0,%1,%2,%3}, {%4,%5,%6,%7}, {%8,%9}, {%0,%1,%2,%3};" \
        : "+f"((c)[0]), "+f"((c)[1]), "+f"((c)[2]), "+f"((c)[3]) \
        : "r"((a).x), "r"((a).y), "r"((a).z), "r"((a).w), "r"(bb0), "r"(bb1))

// ---------------- launch 1: bucket fill (count + scatter in one pass) ----------------
__global__ void k_fill(const int* __restrict__ row0, const int* __restrict__ col0,
                       const int* __restrict__ row1, const int* __restrict__ col1) {
    int p = blockIdx.y;
    const int* row = p ? row1 : row0;
    const int* col = p ? col1 : col0;
    int e = blockIdx.x * blockDim.x + threadIdx.x;
    if (e < N_EDGES) {
        int d = col[e];
        int pos = atomicAdd(&g_deg[p][d], 1);
        g_buck[p][(size_t)d * CAP + pos] = row[e];
    }
}

// ---------------- launch 2: dinv + pool init + x̂ transcode ----------------
__global__ void k_prep(const float* __restrict__ x0, const float* __restrict__ x1) {
    const int p = blockIdx.y;
    const int b = blockIdx.x;
    const int t = threadIdx.x;
    const int i = b * 1024 + t;
    const int lane = t & 31;

    if (i < N_NODES) g_dinv[p][i] = rsqrtf((float)(g_deg[p][i] + 1));   // +1 self loop
    if (b == 0) {
        #pragma unroll
        for (int it = 0; it < 16; it++)
            g_pool[p * NB * DIM + it * 1024 + t] = -FLT_MAX;
    }

    // transcode: x̂ = dinv[src] * x (fp16), coalesced, 32 nodes/warp
    {
        const float4* xs = (const float4*)(p ? x1 : x0);
        const int w = t >> 5;
        const int nb = b * 1024 + w * 32;
        for (int nd = 0; nd < 32; nd++) {
            int i2 = nb + nd;
            if (i2 >= N_NODES) break;
            float s = rsqrtf((float)(g_deg[p][i2] + 1));
            float4 xv = xs[(size_t)i2 * 32 + lane];
            __half2 h0 = __floats2half2_rn(s * xv.x, s * xv.y);
            __half2 h1 = __floats2half2_rn(s * xv.z, s * xv.w);
            uint2 o;
            o.x = *(unsigned*)&h0; o.y = *(unsigned*)&h1;
            g_xh[p][(size_t)i2 * 32 + lane] = o;
        }
    }
}

// ---------------- launch 3: gather, fp16 accumulation (2x2 chains) -> mma-frag fp16 A ----------------
__global__ void k_gather() {
    int p = blockIdx.y;
    const char* xb = (const char*)g_xh[p];       // byte base; row = 256B
    int gw = (blockIdx.x * blockDim.x + threadIdx.x) >> 5;
    int lane = threadIdx.x & 31;
    if (gw >= N_NODES) return;
    const int i = gw;
    const float di = g_dinv[p][i];
    const unsigned lb = (unsigned)lane * 8u;     // lane byte offset within row
    const int* csr = g_buck[p] + (size_t)i * CAP;   // 512B-aligned (CAP*4)

    // chain A seeded with self term; chain B zero
    __half2 a0, a1, b0, b1;
    {
        uint2 u = *(const uint2*)(xb + (unsigned)i * 256u + lb);
        a0 = *(__half2*)&u.x; a1 = *(__half2*)&u.y;
        unsigned z = 0;
        b0 = *(__half2*)&z; b1 = *(__half2*)&z;
    }

    int j = 0;
    const int s1 = g_deg[p][i];
    for (; j + 4 <= s1; j += 4) {
        int4 c4 = *(const int4*)&csr[j];         // aligned LDG.128: 4 indices
        unsigned oa = (unsigned)c4.x * 256u + lb;
        unsigned ob = (unsigned)c4.y * 256u + lb;
        unsigned oc = (unsigned)c4.z * 256u + lb;
        unsigned od = (unsigned)c4.w * 256u + lb;
        uint2 ua = *(const uint2*)(xb + oa);
        uint2 ub = *(const uint2*)(xb + ob);
        uint2 uc = *(const uint2*)(xb + oc);
        uint2 ud = *(const uint2*)(xb + od);
        a0 = __hadd2(a0, *(__half2*)&ua.x); a1 = __hadd2(a1, *(__half2*)&ua.y);
        b0 = __hadd2(b0, *(__half2*)&ub.x); b1 = __hadd2(b1, *(__half2*)&ub.y);
        a0 = __hadd2(a0, *(__half2*)&uc.x); a1 = __hadd2(a1, *(__half2*)&uc.y);
        b0 = __hadd2(b0, *(__half2*)&ud.x); b1 = __hadd2(b1, *(__half2*)&ud.y);
    }
    for (; j < s1; j++) {
        uint2 u = *(const uint2*)(xb + (unsigned)csr[j] * 256u + lb);
        a0 = __hadd2(a0, *(__half2*)&u.x); a1 = __hadd2(a1, *(__half2*)&u.y);
    }

    // merge chains in fp32, scale by dinv[dst], round to fp16 frags
    float2 fa0 = __half22float2(a0), fb0 = __half22float2(b0);
    float2 fa1 = __half22float2(a1), fb1 = __half22float2(b1);
    float sx = (fa0.x + fb0.x) * di;
    float sy = (fa0.y + fb0.y) * di;
    float sz = (fa1.x + fb1.x) * di;
    float sw = (fa1.y + fb1.y) * di;
    __half2 hp0 = __floats2half2_rn(sx, sy);
    __half2 hp1 = __floats2half2_rn(sz, sw);

    // fragment-layout offsets: lane j handles k = j*4..j*4+3
    const int tile = i >> 7;
    const int rb = (i >> 4) & 7;          // 16-row frag within tile
    const int r16 = i & 15;
    const int kc = lane >> 2;             // k-chunk
    const int kl = (lane & 3) * 4;        // k within chunk (0,4,8,12)
    const int lane_f = ((r16 & 7) << 2) + ((kl & 7) >> 1);
    const int reg = ((r16 >> 3) & 1) + ((kl >> 3) << 1);
    const size_t base = ((((size_t)tile * 8 + rb) * 8 + kc) << 8) + (size_t)(lane_f * 8 + reg * 2);

    __half* Ah = g_Ah[p];
    *(__half2*)&Ah[base]     = hp0;       // (k, k+1)
    *(__half2*)&Ah[base + 8] = hp1;       // (k+2, k+3)
}

// ---------------- launch 4 (CAPTURED): mma.sync fp16 GEMM, frag-ordered W smem ----------------
// 512 threads: 16 warps = 8 M-frags x 2 N-halves. W in smem as uint2 frags:
// sW[nb(16)][kc(8)][lane(32)] = {b0h, b1h} -> one LDS.64 + one MMA per (jj,kc).
#define SMEM_GEMM (4096 * 8 + 512)

__global__ void __launch_bounds__(512, 2)
k_gemm_pool(const float* __restrict__ W0, const float* __restrict__ b0,
            const float* __restrict__ W1, const float* __restrict__ b1,
            const int* __restrict__ batch0, const int* __restrict__ batch1) {
    extern __shared__ uint2 sW[];                // 4096 uint2 = 32KB
    float* s_bias = (float*)(sW + 4096);

    const int p = blockIdx.y, tile = blockIdx.x;
    const float* __restrict__ W     = p ? W1 : W0;
    const float* __restrict__ bias  = p ? b1 : b0;
    const int*   __restrict__ batch = p ? batch1 : batch0;
    const int tid = threadIdx.x, lane = tid & 31, w = tid >> 5;
    const int w_m = w & 7, nh = w >> 3;

    // stage W -> fragment-ordered smem (one-time, 8 uint2/thread)
    #pragma unroll
    for (int it = 0; it < 8; it++) {
        int idx = tid + it * 512;                // 0..4095
        int lane_s = idx & 31;
        int kc_s = (idx >> 5) & 7;
        int nb_s = idx >> 8;                     // 0..15
        int n = nb_s * 8 + (lane_s >> 2);
        int k0 = (kc_s * 8 + (lane_s & 3)) * 2;  // pairs at k0,k0+1 and k0+8,k0+9
        float w00 = W[k0 * 128 + n];
        float w01 = W[(k0 + 1) * 128 + n];
        float w10 = W[(k0 + 8) * 128 + n];
        float w11 = W[(k0 + 9) * 128 + n];
        __half2 ph0 = __floats2half2_rn(w00, w01);
        __half2 ph1 = __floats2half2_rn(w10, w11);
        uint2 frag;
        frag.x = *(unsigned*)&ph0; frag.y = *(unsigned*)&ph1;
        sW[idx] = frag;
    }
    if (tid < 128) s_bias[tid] = bias[tid];
    __syncthreads();

    float acc[8][4];
    #pragma unroll
    for (int jj = 0; jj < 8; jj++)
        #pragma unroll
        for (int q = 0; q < 4; q++) acc[jj][q] = 0.f;

    const __half* Ah = g_Ah[p];
    const size_t abase = ((size_t)tile * 8 + w_m) * 8;
    #pragma unroll
    for (int kc = 0; kc < 8; kc++) {
        uint4 ah = *(const uint4*)&Ah[((abase + kc) << 8) + lane * 8];
        #pragma unroll
        for (int jj = 0; jj < 8; jj++) {
            uint2 bf = sW[(((nh * 8 + jj) * 8 + kc) << 5) + lane];   // one LDS.64
            MMA4(acc[jj], ah, bf.x, bf.y);
        }
    }

    // epilogue: segment_max into pool
    const int r_base = tile * 128 + w_m * 16;
    float* pool = &g_pool[p * NB * DIM];
    const bool full = (r_base + 15 < N_NODES);
    const bool any  = (r_base < N_NODES);
    int btA = any ? batch[r_base] : -1;
    int btB = full ? batch[r_base + 15] : -2;

    if (full && btA == btB) {
        #pragma unroll
        for (int jj = 0; jj < 8; jj++) {
            float m0 = fmaxf(acc[jj][0], acc[jj][2]);
            float m1 = fmaxf(acc[jj][1], acc[jj][3]);
            #pragma unroll
            for (int o = 4; o <= 16; o <<= 1) {
                m0 = fmaxf(m0, __shfl_xor_sync(0xffffffffu, m0, o));
                m1 = fmaxf(m1, __shfl_xor_sync(0xffffffffu, m1, o));
            }
            if ((lane >> 2) == 0) {
                int c = (nh * 8 + jj) * 8 + (lane & 3) * 2;
                atomicMaxFloat(&pool[btA * DIM + c],     lrelu(m0 + s_bias[c]));
                atomicMaxFloat(&pool[btA * DIM + c + 1], lrelu(m1 + s_bias[c + 1]));
            }
        }
    } else if (any) {
        int r0 = r_base + (lane >> 2), r1 = r0 + 8;
        int bt0 = (r0 < N_NODES) ? batch[r0] : -1;
        int bt1 = (r1 < N_NODES) ? batch[r1] : -1;
        #pragma unroll
        for (int jj = 0; jj < 8; jj++) {
            int c = (nh * 8 + jj) * 8 + (lane & 3) * 2;
            if (bt0 >= 0) {
                atomicMaxFloat(&pool[bt0 * DIM + c],     lrelu(acc[jj][0] + s_bias[c]));
                atomicMaxFloat(&pool[bt0 * DIM + c + 1], lrelu(acc[jj][1] + s_bias[c + 1]));
            }
            if (bt1 >= 0) {
                atomicMaxFloat(&pool[bt1 * DIM + c],     lrelu(acc[jj][2] + s_bias[c]));
                atomicMaxFloat(&pool[bt1 * DIM + c + 1], lrelu(acc[jj][3] + s_bias[c + 1]));
            }
        }
    }
}

// ---------------- launch 5: fused tail MLP (fcp both branches -> fc1 -> fc2 -> out) ----------------
__global__ void __launch_bounds__(256)
k_tail(const float* __restrict__ fcp1W, const float* __restrict__ fcp1B,
       const float* __restrict__ fcp2W, const float* __restrict__ fcp2B,
       const float* __restrict__ fc1W,  const float* __restrict__ fc1B,
       const float* __restrict__ fc2W,  const float* __restrict__ fc2B,
       const float* __restrict__ outW,  const float* __restrict__ outB,
       float* __restrict__ out) {
    const int r = blockIdx.x, t = threadIdx.x;
    __shared__ float pl[256];   // pool rows: [0:128)=branch0, [128:256)=branch1
    __shared__ float c[256];    // concat(g1, g2)
    __shared__ float c1s[256];
    __shared__ float c2s[64];

    pl[t] = g_pool[(t < 128 ? 0 : NB * DIM) + r * 128 + (t & 127)];
    __syncthreads();

    {   // fc_p per branch
        const float* Wp = (t < 128) ? fcp1W : fcp2W;
        const float* bp = (t < 128) ? fcp1B : fcp2B;
        const float* src = (t < 128) ? pl : (pl + 128);
        int d = t & 127;
        float s = bp[d];
        #pragma unroll 8
        for (int k = 0; k < 128; k++) s += src[k] * Wp[k * 128 + d];
        c[t] = lrelu(s);
    }
    __syncthreads();

    {   // fc1: 256 -> 256
        float s = fc1B[t];
        #pragma unroll 8
        for (int k = 0; k < 256; k++) s += c[k] * fc1W[k * 256 + t];
        c1s[t] = lrelu(s);
    }
    __syncthreads();

    if (t < 64) {   // fc2: 256 -> 64
        float s = fc2B[t];
        #pragma unroll 8
        for (int k = 0; k < 256; k++) s += c1s[k] * fc2W[k * 64 + t];
        c2s[t] = lrelu(s);
    }
    __syncthreads();

    if (t < 32) {   // out: 64 -> 1 + sigmoid
        float v = c2s[t] * outW[t] + c2s[t + 32] * outW[t + 32];
        #pragma unroll
        for (int o = 16; o; o >>= 1) v += __shfl_xor_sync(0xffffffffu, v, o);
        if (t == 0) out[r] = 1.f / (1.f + expf(-(v + outB[0])));
    }
}

// ---------------- host launcher ----------------
extern "C" void kernel_launch(void* const* d_in, const int* in_sizes, int n_in,
                              void* d_out, int out_size) {
    int ix[2], ie[2], ib[2];
    if (in_sizes[1] == N_NODES * DIM) {
        ix[0] = 0; ix[1] = 1; ie[0] = 2; ie[1] = 3; ib[0] = 4; ib[1] = 5;   // dict order
    } else {
        ix[0] = 0; ie[0] = 1; ib[0] = 2; ix[1] = 3; ie[1] = 4; ib[1] = 5;   // signature order
    }
    const float* x0 = (const float*)d_in[ix[0]];
    const float* x1 = (const float*)d_in[ix[1]];
    const int* row0 = (const int*)d_in[ie[0]];
    const int* col0 = row0 + N_EDGES;
    const int* row1 = (const int*)d_in[ie[1]];
    const int* col1 = row1 + N_EDGES;
    const int* bat0 = (const int*)d_in[ib[0]];
    const int* bat1 = (const int*)d_in[ib[1]];

    const float* convW0 = (const float*)d_in[6];
    const float* convB0 = (const float*)d_in[7];
    const float* convW1 = (const float*)d_in[8];
    const float* convB1 = (const float*)d_in[9];
    const float* fcp1W = (const float*)d_in[10];
    const float* fcp1B = (const float*)d_in[11];
    const float* fcp2W = (const float*)d_in[12];
    const float* fcp2B = (const float*)d_in[13];
    const float* fc1W  = (const float*)d_in[14];
    const float* fc1B  = (const float*)d_in[15];
    const float* fc2W  = (const float*)d_in[16];
    const float* fc2B  = (const float*)d_in[17];
    const float* outW  = (const float*)d_in[18];
    const float* outB  = (const float*)d_in[19];

    static bool attr_done = false;
    if (!attr_done) {
        cudaFuncSetAttribute(k_gemm_pool, cudaFuncAttributeMaxDynamicSharedMemorySize, SMEM_GEMM);
        attr_done = true;
    }

    void* degPtr = nullptr;
    cudaGetSymbolAddress(&degPtr, g_deg);
    cudaMemsetAsync(degPtr, 0, 2 * N_NODES * sizeof(int));

    k_fill<<<dim3((N_EDGES + 255) / 256, 2), 256>>>(row0, col0, row1, col1); // launch 1
    k_prep<<<dim3(PREP_BLOCKS, 2), 1024>>>(x0, x1);                          // launch 2
    k_gather<<<dim3((N_NODES * 32 + 255) / 256, 2), 256>>>();                // launch 3
    k_gemm_pool<<<dim3(TILES, 2), 512, SMEM_GEMM>>>(convW0, convB0, convW1, convB1, bat0, bat1); // launch 4 (captured)
    k_tail<<<NB, 256>>>(fcp1W, fcp1B, fcp2W, fcp2B, fc1W, fc1B, fc2W, fc2B,
                        outW, outB, (float*)d_out);                          // launch 5
}